// round 16
// baseline (speedup 1.0000x reference)
#include <cuda_runtime.h>
#include <cuda_fp16.h>
#include <math.h>
#include <stdint.h>

// ---------------- problem constants ----------------
#define HDIM    2048
#define NE      64           // experts (GEMM N)
#define TM      64           // tokens per CTA (GEMM M)
#define KB      32           // K per chunk (floats)
#define KSPLIT  2
#define KHALF   (HDIM/KSPLIT)        // 1024
#define NCHK    (KHALF/KB)           // 32
#define THREADS 128
#define GAP_TH  4e-3f
#define FLAG_CAP 4096
#define MAXCAND 8
#define NTILE   256                   // N / TM

// ---- 4-stage smem pipeline ----
#define NSTAGE   4
#define XPITCHW  36
#define WPITCHW  20
#define XBYTES   (TM * XPITCHW * 4)       // 9216
#define WBYTES   (NE * WPITCHW * 4)       // 5120
#define STAGEB   (XBYTES + WBYTES)        // 14336
#define SMEM_DYN (NSTAGE * STAGEB)        // 57344
#define LSP 65

__device__ float g_eload[NE];
__device__ float g_zsum;
__device__ int   g_done;
__device__ int   g_nflag;
__device__ int   g_tilecnt[NTILE];
__device__ int   g_flags[FLAG_CAP];
__device__ float g_flag_lg[FLAG_CAP][NE];
__device__ uint32_t g_wh[NE * HDIM / 2];        // W half2, (k,k+4)-paired
__device__ float g_partial[512 * TM * NE];      // 8 MB split-K partials

// ---- one-time W fp16 convert (pair-permuted) + scratch zeroing ----
__global__ __launch_bounds__(128) void prep_kernel(const float* __restrict__ W) {
    const int e = blockIdx.x;
    const int tid = threadIdx.x;
    if (e == 0) {
        if (tid < NE) g_eload[tid] = 0.0f;
        if (tid == 0) { g_zsum = 0.0f; g_done = 0; g_nflag = 0; }
        for (int i = tid; i < NTILE; i += 128) g_tilecnt[i] = 0;
    }
    const int c  = tid >> 1;
    const int ks = tid & 1;
    const float* wr = &W[(size_t)e * HDIM + c * 32 + ks * 16];
    float4 v[4];
#pragma unroll
    for (int i = 0; i < 4; i++) v[i] = *reinterpret_cast<const float4*>(wr + i * 4);
    uint32_t H[8];
#pragma unroll
    for (int i = 0; i < 4; i++) {
        __half2 a = __floats2half2_rn(v[i].x, v[i].y);
        __half2 b = __floats2half2_rn(v[i].z, v[i].w);
        H[i * 2]     = *reinterpret_cast<uint32_t*>(&a);
        H[i * 2 + 1] = *reinterpret_cast<uint32_t*>(&b);
    }
    uint32_t o[8];
#pragma unroll
    for (int q = 0; q < 4; q++) {
        o[2 * q]     = H[q];
        o[2 * q + 1] = H[q + 4];
    }
    uint32_t* dst = &g_wh[e * (HDIM / 2) + c * 16 + ks * 8];
    *reinterpret_cast<uint4*>(dst)     = *reinterpret_cast<uint4*>(o);
    *reinterpret_cast<uint4*>(dst + 4) = *reinterpret_cast<uint4*>(o + 4);
}

__device__ __forceinline__ uint32_t smem_u32(const void* p) {
    uint32_t a;
    asm("{ .reg .u64 t; cvta.to.shared.u64 t, %1; cvt.u32.u64 %0, t; }" : "=r"(a) : "l"(p));
    return a;
}
__device__ __forceinline__ void cp16(uint32_t dst, const void* src) {
    asm volatile("cp.async.cg.shared.global [%0], [%1], 16;" :: "r"(dst), "l"(src));
}
__device__ __forceinline__ void cp_commit() {
    asm volatile("cp.async.commit_group;");
}
__device__ __forceinline__ void cp_wait2() {
    asm volatile("cp.async.wait_group 2;" ::: "memory");
}
__device__ __forceinline__ void mma_f32acc(float* d, const uint32_t* a, uint32_t b0, uint32_t b1) {
    asm volatile(
        "mma.sync.aligned.m16n8k16.row.col.f32.f16.f16.f32 "
        "{%0,%1,%2,%3}, {%4,%5,%6,%7}, {%8,%9}, {%0,%1,%2,%3};"
        : "+f"(d[0]), "+f"(d[1]), "+f"(d[2]), "+f"(d[3])
        : "r"(a[0]), "r"(a[1]), "r"(a[2]), "r"(a[3]), "r"(b0), "r"(b1));
}
__device__ __forceinline__ uint32_t cvt2(float2 v) {
    __half2 h = __floats2half2_rn(v.x, v.y);
    return *reinterpret_cast<uint32_t*>(&h);
}

// ---------------- split-K fp16 GEMM + fused combine/epilogue ----------------
__global__ __launch_bounds__(THREADS, 3) void gateK_kernel(
    const float* __restrict__ x, float* __restrict__ out, int N)
{
    extern __shared__ __align__(16) char smem[];
    const uint32_t sbase = smem_u32(smem);
    const int tid  = threadIdx.x;
    const int wid  = tid >> 5;
    const int lane = tid & 31;
    const int grp  = lane >> 2;
    const int qid  = lane & 3;
    const int b    = blockIdx.x >> 1;
    const int h    = blockIdx.x & 1;
    const int tok0 = b * TM;
    const int koff = h * KHALF;
    const int woff = h * (KHALF / 2);

    float acc[8][4];
#pragma unroll
    for (int nt = 0; nt < 8; nt++)
#pragma unroll
        for (int i = 0; i < 4; i++) acc[nt][i] = 0.0f;

    auto issue_stage = [&](int c) {
        const int buf = c & (NSTAGE - 1);
        const uint32_t xdst0 = sbase + buf * STAGEB;
        const uint32_t wdst0 = sbase + buf * STAGEB + XBYTES;
#pragma unroll
        for (int i = 0; i < 4; i++) {
            int q = tid + i * THREADS;
            int row = q >> 3, qi = q & 7;
            cp16(xdst0 + row * 144 + qi * 16,
                 &x[(size_t)(tok0 + row) * HDIM + koff + c * KB + qi * 4]);
        }
#pragma unroll
        for (int i = 0; i < 2; i++) {
            int q = tid + i * THREADS;
            int row = q >> 2, qi = q & 3;
            cp16(wdst0 + row * 80 + qi * 16,
                 &g_wh[row * (HDIM / 2) + woff + c * (KB / 2) + qi * 4]);
        }
        cp_commit();
    };

    issue_stage(0);
    issue_stage(1);
    issue_stage(2);

    const int r0 = wid * 16 + grp;
    const int r1 = r0 + 8;

    for (int c = 0; c < NCHK; c++) {
        const int buf = c & (NSTAGE - 1);
        cp_wait2();
        __syncthreads();

        if (c + 3 < NCHK) issue_stage(c + 3);
        else cp_commit();

        const float*    xs = reinterpret_cast<const float*>(smem + buf * STAGEB);
        const uint32_t* wh = reinterpret_cast<const uint32_t*>(smem + buf * STAGEB + XBYTES);

#pragma unroll
        for (int ks = 0; ks < 2; ks++) {
            const int h2k = ks * 8 + qid;
            uint32_t aH[4];
            aH[0] = cvt2(*reinterpret_cast<const float2*>(&xs[r0 * XPITCHW + 2 * h2k]));
            aH[1] = cvt2(*reinterpret_cast<const float2*>(&xs[r1 * XPITCHW + 2 * h2k]));
            aH[2] = cvt2(*reinterpret_cast<const float2*>(&xs[r0 * XPITCHW + 2 * h2k + 8]));
            aH[3] = cvt2(*reinterpret_cast<const float2*>(&xs[r1 * XPITCHW + 2 * h2k + 8]));
            const int pp = (ks * 4 + qid) * 2;
#pragma unroll
            for (int nt = 0; nt < 8; nt++) {
                const int n0 = nt * 8 + grp;
                uint2 bb = *reinterpret_cast<const uint2*>(&wh[n0 * WPITCHW + pp]);
                mma_f32acc(acc[nt], aH, bb.x, bb.y);
            }
        }
        __syncthreads();
    }

    float* ls = reinterpret_cast<float*>(smem);   // [64][65]
#pragma unroll
    for (int nt = 0; nt < 8; nt++) {
        const int cb = nt * 8 + qid * 2;
        ls[r0 * LSP + cb]     = acc[nt][0];
        ls[r0 * LSP + cb + 1] = acc[nt][1];
        ls[r1 * LSP + cb]     = acc[nt][2];
        ls[r1 * LSP + cb + 1] = acc[nt][3];
    }
    __syncthreads();

    // store partial (coalesced)
    float* dst = &g_partial[(size_t)blockIdx.x * TM * NE];
#pragma unroll
    for (int i = 0; i < TM * NE / THREADS; i++) {
        int idx = tid + i * THREADS;
        dst[idx] = ls[(idx >> 6) * LSP + (idx & 63)];
    }

    // split-K rendezvous: second finisher combines + runs epilogue
    __shared__ int s_old;
    __threadfence();
    __syncthreads();
    if (tid == 0) s_old = atomicAdd(&g_tilecnt[b], 1);
    __syncthreads();
    if (s_old == 0) return;
    __threadfence();   // acquire peer partial

    const float* po = &g_partial[(size_t)(b * 2 + (1 - h)) * TM * NE];
#pragma unroll
    for (int i = 0; i < TM * NE / THREADS; i++) {
        int idx = tid + i * THREADS;
        ls[(idx >> 6) * LSP + (idx & 63)] += po[idx];
    }
    __syncthreads();

    // ---- per-token epilogue ----
    if (tid < TM) {
        float lg[NE];
#pragma unroll
        for (int e = 0; e < NE; e++) lg[e] = ls[tid * LSP + e];

        float v1 = -1e30f, v2 = -1e30f, v3 = -1e30f;
        int i1 = 0, i2 = 0;
#pragma unroll
        for (int e = 0; e < NE; e++) {
            float le = lg[e];
            if (le > v1)      { v3 = v2; v2 = v1; i2 = i1; v1 = le; i1 = e; }
            else if (le > v2) { v3 = v2; v2 = le; i2 = e; }
            else if (le > v3) { v3 = le; }
        }
        const int tg = tok0 + tid;

        if ((v1 - v2 < GAP_TH) || (v2 - v3 < GAP_TH)) {
            int slot = atomicAdd(&g_nflag, 1);
            if (slot < FLAG_CAP) {
                g_flags[slot] = tg;
#pragma unroll
                for (int e = 0; e < NE; e++) g_flag_lg[slot][e] = lg[e];
            }
        }

        const float m = v1;
        float s = 0.0f;
#pragma unroll
        for (int e = 0; e < NE; e++) { lg[e] = expf(lg[e] - m); s += lg[e]; }
        const float inv = 1.0f / s;
#pragma unroll
        for (int e = 0; e < NE; e++) ls[tid * LSP + e] = lg[e] * inv;

        const float p1s = inv;
        const float p2s = expf(v2 - m) * inv;
        const float s1 = 1.0f / (1.0f + expf(p2s - p1s));

        out[tg * 2 + 0] = s1;
        out[tg * 2 + 1] = 1.0f - s1;
        out[2 * N + tg * 2 + 0] = (float)i1;
        out[2 * N + tg * 2 + 1] = (float)i2;

        float lse = m + logf(s);
        float zz = lse * lse;
#pragma unroll
        for (int o = 16; o > 0; o >>= 1)
            zz += __shfl_xor_sync(0xFFFFFFFFu, zz, o);
        if (lane == 0) atomicAdd(&g_zsum, zz);
    }
    __syncthreads();

    if (tid < NE) {
        float cs = 0.0f;
#pragma unroll 8
        for (int t = 0; t < TM; t++) cs += ls[t * LSP + tid];
        atomicAdd(&g_eload[tid], cs);
    }
    __threadfence();
    __syncthreads();

    if (tid == 0) {
        int d = atomicAdd(&g_done, 1);
        if (d == NTILE - 1) {
            const float invN = 1.0f / (float)N;
            float lb = 0.0f;
            for (int e = 0; e < NE; e++) {
                float dd = g_eload[e] * invN - (1.0f / 64.0f);
                lb += dd * dd;
            }
            out[(size_t)4 * N] = 0.01f * lb + 1e-4f * (g_zsum * invN);
        }
    }
}

// ---------------- block-per-token fixup (parallel scans) ----------------
__device__ __forceinline__ void twosum(float& s, float& c, float p) {
    float t  = s + p;
    float bv = t - s;
    c += (s - (t - bv)) + (p - bv);
    s = t;
}

__global__ __launch_bounds__(128) void fixup_kernel(
    const float* __restrict__ x, const float* __restrict__ W,
    float* __restrict__ out, int N)
{
    __shared__ float4 xs4[HDIM / 4];
    __shared__ float  lgs[NE];
    __shared__ int    cand[MAXCAND];
    __shared__ int    ncand_sh;
    __shared__ float  cval[MAXCAND];
    __shared__ int    top_i1, top_i2;
    __shared__ float  red[4];
    const int tid  = threadIdx.x;
    const int wid  = tid >> 5;
    const int lane = tid & 31;
    const int nf   = min(g_nflag, FLAG_CAP);

    for (int fi = blockIdx.x; fi < nf; fi += gridDim.x) {
        const int tg = g_flags[fi];

        const float4* xr4 = reinterpret_cast<const float4*>(&x[(size_t)tg * HDIM]);
#pragma unroll
        for (int i = 0; i < 4; i++)
            xs4[tid + i * 128] = xr4[tid + i * 128];
        if (tid < NE) lgs[tid] = g_flag_lg[fi][tid];
        __syncthreads();

        // warp 0: parallel top-2 values + ballot candidate list
        if (wid == 0) {
            float a = lgs[lane], bb = lgs[lane + 32];
            float v1 = fmaxf(a, bb), v2 = fminf(a, bb);
#pragma unroll
            for (int o = 16; o > 0; o >>= 1) {
                float w1 = __shfl_xor_sync(0xFFFFFFFFu, v1, o);
                float w2 = __shfl_xor_sync(0xFFFFFFFFu, v2, o);
                if (w1 > v1) { v2 = fmaxf(v1, w2); v1 = w1; }
                else         { v2 = fmaxf(v2, w1); }
            }
            float cut = v2 - 2.0f * GAP_TH;
            uint32_t mA = __ballot_sync(0xFFFFFFFFu, a > cut);
            uint32_t mB = __ballot_sync(0xFFFFFFFFu, bb > cut);
            if (lane == 0) {
                int nc = 0;
                while (mA && nc < MAXCAND) { int e = __ffs(mA) - 1; mA &= mA - 1; cand[nc++] = e; }
                while (mB && nc < MAXCAND) { int e = __ffs(mB) - 1; mB &= mB - 1; cand[nc++] = e + 32; }
                ncand_sh = nc;
            }
        }
        __syncthreads();
        const int nc = ncand_sh;

        // 4 warps x concurrent candidates; fully-unrolled MLP-16 dot
        for (int ci = wid; ci < nc; ci += 4) {
            const float4* wr4 = reinterpret_cast<const float4*>(&W[(size_t)cand[ci] * HDIM]);
            float s0 = 0, c0 = 0, s1 = 0, c1 = 0, s2 = 0, c2 = 0, s3 = 0, c3 = 0;
#pragma unroll
            for (int j = 0; j < 16; j++) {
                float4 a = xs4[lane + j * 32];
                float4 bb = wr4[lane + j * 32];
                float p0 = a.x * bb.x; float e0 = fmaf(a.x, bb.x, -p0); twosum(s0, c0, p0); c0 += e0;
                float p1 = a.y * bb.y; float e1 = fmaf(a.y, bb.y, -p1); twosum(s1, c1, p1); c1 += e1;
                float p2 = a.z * bb.z; float e2 = fmaf(a.z, bb.z, -p2); twosum(s2, c2, p2); c2 += e2;
                float p3 = a.w * bb.w; float e3 = fmaf(a.w, bb.w, -p3); twosum(s3, c3, p3); c3 += e3;
            }
            twosum(s0, c0, s1); c0 += c1;
            twosum(s2, c2, s3); c2 += c3;
            twosum(s0, c0, s2); c0 += c2;
#pragma unroll
            for (int o = 16; o > 0; o >>= 1) {
                float ss = __shfl_xor_sync(0xFFFFFFFFu, s0, o);
                float cc = __shfl_xor_sync(0xFFFFFFFFu, c0, o);
                twosum(s0, c0, ss);
                c0 += cc;
            }
            if (lane == 0) cval[ci] = s0 + c0;
        }
        __syncthreads();

        // exact top-2 is among the candidates (cut covers 2*GAP_TH below v2)
        if (tid == 0) {
            for (int ci = 0; ci < nc; ci++) lgs[cand[ci]] = cval[ci];
            float v1 = -1e30f, v2 = -1e30f; int i1 = 0, i2 = 0;
            for (int ci = 0; ci < nc; ci++) {
                float le = cval[ci]; int e = cand[ci];
                if (le > v1 || (le == v1 && e < i1)) { v2 = v1; i2 = i1; v1 = le; i1 = e; }
                else if (le > v2 || (le == v2 && e < i2)) { v2 = le; i2 = e; }
            }
            top_i1 = i1; top_i2 = i2;
        }
        __syncthreads();

        // block-parallel softmax sum over all 64 (corrected) logits
        float ev = 0.0f;
        const float m = lgs[top_i1];
        if (tid < NE) ev = expf(lgs[tid] - m);
#pragma unroll
        for (int o = 16; o > 0; o >>= 1)
            ev += __shfl_xor_sync(0xFFFFFFFFu, ev, o);
        if (tid < NE && lane == 0) red[wid] = ev;
        __syncthreads();

        if (tid == 0) {
            float s = red[0] + red[1];
            float inv = 1.0f / s;
            float p1 = inv;
            float p2 = expf(lgs[top_i2] - m) * inv;
            float s1 = 1.0f / (1.0f + expf(p2 - p1));
            out[tg * 2 + 0] = s1;
            out[tg * 2 + 1] = 1.0f - s1;
            out[2 * N + tg * 2 + 0] = (float)top_i1;
            out[2 * N + tg * 2 + 1] = (float)top_i2;
        }
        __syncthreads();
    }
}

extern "C" void kernel_launch(void* const* d_in, const int* in_sizes, int n_in,
                              void* d_out, int out_size) {
    const float* x = (const float*)d_in[0];
    const float* W = (const float*)d_in[1];
    float* out = (float*)d_out;
    const int N = in_sizes[0] / HDIM;   // 16384

    cudaFuncSetAttribute(gateK_kernel, cudaFuncAttributeMaxDynamicSharedMemorySize, SMEM_DYN);
    prep_kernel<<<NE, 128>>>(W);
    gateK_kernel<<<(N / TM) * KSPLIT, THREADS, SMEM_DYN>>>(x, out, N);
    fixup_kernel<<<512, 128>>>(x, W, out, N);
}

// round 17
// speedup vs baseline: 1.4757x; 1.4757x over previous
#include <cuda_runtime.h>
#include <cuda_fp16.h>
#include <math.h>
#include <stdint.h>

// ---------------- problem constants ----------------
#define HDIM    2048
#define NE      64           // experts (GEMM N)
#define TM      64           // tokens per CTA (GEMM M)
#define KB      32           // K per chunk (floats)
#define KSPLIT  2
#define KHALF   (HDIM/KSPLIT)        // 1024
#define NCHK    (KHALF/KB)           // 32
#define THREADS 128
#define GAP_TH  4e-3f
#define FLAG_CAP 4096
#define MAXCAND 8

// ---- 4-stage smem pipeline ----
#define NSTAGE   4
#define XPITCHW  36
#define WPITCHW  20
#define XBYTES   (TM * XPITCHW * 4)       // 9216
#define WBYTES   (NE * WPITCHW * 4)       // 5120
#define STAGEB   (XBYTES + WBYTES)        // 14336
#define SMEM_DYN (NSTAGE * STAGEB)        // 57344
#define LSP 65

__device__ float g_eload[NE];
__device__ float g_zsum;
__device__ int   g_done;
__device__ int   g_nflag;
__device__ int   g_flags[FLAG_CAP];
__device__ float g_flag_lg[FLAG_CAP][NE];
__device__ uint32_t g_wh[NE * HDIM / 2];        // W half2, (k,k+4)-paired
__device__ float g_partial[512 * TM * NE];      // 8 MB split-K partials

// ---- one-time W fp16 convert (pair-permuted) + scratch zeroing ----
__global__ __launch_bounds__(128) void prep_kernel(const float* __restrict__ W) {
    const int e = blockIdx.x;
    const int tid = threadIdx.x;
    if (e == 0) {
        if (tid < NE) g_eload[tid] = 0.0f;
        if (tid == 0) { g_zsum = 0.0f; g_done = 0; g_nflag = 0; }
    }
    const int c  = tid >> 1;
    const int ks = tid & 1;
    const float* wr = &W[(size_t)e * HDIM + c * 32 + ks * 16];
    float4 v[4];
#pragma unroll
    for (int i = 0; i < 4; i++) v[i] = *reinterpret_cast<const float4*>(wr + i * 4);
    uint32_t H[8];
#pragma unroll
    for (int i = 0; i < 4; i++) {
        __half2 a = __floats2half2_rn(v[i].x, v[i].y);
        __half2 b = __floats2half2_rn(v[i].z, v[i].w);
        H[i * 2]     = *reinterpret_cast<uint32_t*>(&a);
        H[i * 2 + 1] = *reinterpret_cast<uint32_t*>(&b);
    }
    uint32_t o[8];
#pragma unroll
    for (int q = 0; q < 4; q++) {
        o[2 * q]     = H[q];
        o[2 * q + 1] = H[q + 4];
    }
    uint32_t* dst = &g_wh[e * (HDIM / 2) + c * 16 + ks * 8];
    *reinterpret_cast<uint4*>(dst)     = *reinterpret_cast<uint4*>(o);
    *reinterpret_cast<uint4*>(dst + 4) = *reinterpret_cast<uint4*>(o + 4);
}

__device__ __forceinline__ uint32_t smem_u32(const void* p) {
    uint32_t a;
    asm("{ .reg .u64 t; cvta.to.shared.u64 t, %1; cvt.u32.u64 %0, t; }" : "=r"(a) : "l"(p));
    return a;
}
__device__ __forceinline__ void cp16(uint32_t dst, const void* src) {
    asm volatile("cp.async.cg.shared.global [%0], [%1], 16;" :: "r"(dst), "l"(src));
}
__device__ __forceinline__ void cp_commit() {
    asm volatile("cp.async.commit_group;");
}
__device__ __forceinline__ void cp_wait2() {
    asm volatile("cp.async.wait_group 2;" ::: "memory");
}
__device__ __forceinline__ void mma_f32acc(float* d, const uint32_t* a, uint32_t b0, uint32_t b1) {
    asm volatile(
        "mma.sync.aligned.m16n8k16.row.col.f32.f16.f16.f32 "
        "{%0,%1,%2,%3}, {%4,%5,%6,%7}, {%8,%9}, {%0,%1,%2,%3};"
        : "+f"(d[0]), "+f"(d[1]), "+f"(d[2]), "+f"(d[3])
        : "r"(a[0]), "r"(a[1]), "r"(a[2]), "r"(a[3]), "r"(b0), "r"(b1));
}
__device__ __forceinline__ uint32_t cvt2(float2 v) {
    __half2 h = __floats2half2_rn(v.x, v.y);
    return *reinterpret_cast<uint32_t*>(&h);
}

// ---------------- split-K fp16 GEMM: partial logits ----------------
__global__ __launch_bounds__(THREADS, 3) void gateK_kernel(
    const float* __restrict__ x, int N)
{
    extern __shared__ __align__(16) char smem[];
    const uint32_t sbase = smem_u32(smem);
    const int tid  = threadIdx.x;
    const int wid  = tid >> 5;
    const int lane = tid & 31;
    const int grp  = lane >> 2;
    const int qid  = lane & 3;
    const int b    = blockIdx.x >> 1;
    const int h    = blockIdx.x & 1;
    const int tok0 = b * TM;
    const int koff = h * KHALF;
    const int woff = h * (KHALF / 2);

    float acc[8][4];
#pragma unroll
    for (int nt = 0; nt < 8; nt++)
#pragma unroll
        for (int i = 0; i < 4; i++) acc[nt][i] = 0.0f;

    auto issue_stage = [&](int c) {
        const int buf = c & (NSTAGE - 1);
        const uint32_t xdst0 = sbase + buf * STAGEB;
        const uint32_t wdst0 = sbase + buf * STAGEB + XBYTES;
#pragma unroll
        for (int i = 0; i < 4; i++) {
            int q = tid + i * THREADS;
            int row = q >> 3, qi = q & 7;
            cp16(xdst0 + row * 144 + qi * 16,
                 &x[(size_t)(tok0 + row) * HDIM + koff + c * KB + qi * 4]);
        }
#pragma unroll
        for (int i = 0; i < 2; i++) {
            int q = tid + i * THREADS;
            int row = q >> 2, qi = q & 3;
            cp16(wdst0 + row * 80 + qi * 16,
                 &g_wh[row * (HDIM / 2) + woff + c * (KB / 2) + qi * 4]);
        }
        cp_commit();
    };

    issue_stage(0);
    issue_stage(1);
    issue_stage(2);

    const int r0 = wid * 16 + grp;
    const int r1 = r0 + 8;

    for (int c = 0; c < NCHK; c++) {
        const int buf = c & (NSTAGE - 1);
        cp_wait2();
        __syncthreads();

        if (c + 3 < NCHK) issue_stage(c + 3);
        else cp_commit();

        const float*    xs = reinterpret_cast<const float*>(smem + buf * STAGEB);
        const uint32_t* wh = reinterpret_cast<const uint32_t*>(smem + buf * STAGEB + XBYTES);

#pragma unroll
        for (int ks = 0; ks < 2; ks++) {
            const int h2k = ks * 8 + qid;
            uint32_t aH[4];
            aH[0] = cvt2(*reinterpret_cast<const float2*>(&xs[r0 * XPITCHW + 2 * h2k]));
            aH[1] = cvt2(*reinterpret_cast<const float2*>(&xs[r1 * XPITCHW + 2 * h2k]));
            aH[2] = cvt2(*reinterpret_cast<const float2*>(&xs[r0 * XPITCHW + 2 * h2k + 8]));
            aH[3] = cvt2(*reinterpret_cast<const float2*>(&xs[r1 * XPITCHW + 2 * h2k + 8]));
            const int pp = (ks * 4 + qid) * 2;
#pragma unroll
            for (int nt = 0; nt < 8; nt++) {
                const int n0 = nt * 8 + grp;
                uint2 bb = *reinterpret_cast<const uint2*>(&wh[n0 * WPITCHW + pp]);
                mma_f32acc(acc[nt], aH, bb.x, bb.y);
            }
        }
        __syncthreads();
    }

    float* ls = reinterpret_cast<float*>(smem);   // [64][65]
#pragma unroll
    for (int nt = 0; nt < 8; nt++) {
        const int cb = nt * 8 + qid * 2;
        ls[r0 * LSP + cb]     = acc[nt][0];
        ls[r0 * LSP + cb + 1] = acc[nt][1];
        ls[r1 * LSP + cb]     = acc[nt][2];
        ls[r1 * LSP + cb + 1] = acc[nt][3];
    }
    __syncthreads();

    float* dst = &g_partial[(size_t)blockIdx.x * TM * NE];
#pragma unroll
    for (int i = 0; i < TM * NE / THREADS; i++) {
        int idx = tid + i * THREADS;
        dst[idx] = ls[(idx >> 6) * LSP + (idx & 63)];
    }
}

// ---------------- combine partials + epilogue + loss ----------------
__global__ __launch_bounds__(128) void combine_kernel(float* __restrict__ out, int N)
{
    __shared__ float ls[TM * LSP];
    const int tid  = threadIdx.x;
    const int lane = tid & 31;
    const int b    = blockIdx.x;
    const int tok0 = b * TM;

    const float* p0 = &g_partial[(size_t)(b * 2 + 0) * TM * NE];
    const float* p1 = &g_partial[(size_t)(b * 2 + 1) * TM * NE];
#pragma unroll
    for (int i = 0; i < TM * NE / 128; i++) {
        int idx = tid + i * 128;
        ls[(idx >> 6) * LSP + (idx & 63)] = p0[idx] + p1[idx];
    }
    __syncthreads();

    if (tid < TM) {
        float lg[NE];
#pragma unroll
        for (int e = 0; e < NE; e++) lg[e] = ls[tid * LSP + e];

        float v1 = -1e30f, v2 = -1e30f, v3 = -1e30f;
        int i1 = 0, i2 = 0;
#pragma unroll
        for (int e = 0; e < NE; e++) {
            float le = lg[e];
            if (le > v1)      { v3 = v2; v2 = v1; i2 = i1; v1 = le; i1 = e; }
            else if (le > v2) { v3 = v2; v2 = le; i2 = e; }
            else if (le > v3) { v3 = le; }
        }
        const int tg = tok0 + tid;

        if ((v1 - v2 < GAP_TH) || (v2 - v3 < GAP_TH)) {
            int slot = atomicAdd(&g_nflag, 1);
            if (slot < FLAG_CAP) {
                g_flags[slot] = tg;
#pragma unroll
                for (int e = 0; e < NE; e++) g_flag_lg[slot][e] = lg[e];
            }
        }

        const float m = v1;
        float s = 0.0f;
#pragma unroll
        for (int e = 0; e < NE; e++) { lg[e] = expf(lg[e] - m); s += lg[e]; }
        const float inv = 1.0f / s;
#pragma unroll
        for (int e = 0; e < NE; e++) ls[tid * LSP + e] = lg[e] * inv;

        const float p1s = inv;
        const float p2s = expf(v2 - m) * inv;
        const float s1 = 1.0f / (1.0f + expf(p2s - p1s));

        out[tg * 2 + 0] = s1;
        out[tg * 2 + 1] = 1.0f - s1;
        out[2 * N + tg * 2 + 0] = (float)i1;
        out[2 * N + tg * 2 + 1] = (float)i2;

        float lse = m + logf(s);
        float zz = lse * lse;
#pragma unroll
        for (int o = 16; o > 0; o >>= 1)
            zz += __shfl_xor_sync(0xFFFFFFFFu, zz, o);
        if (lane == 0) atomicAdd(&g_zsum, zz);
    }
    __syncthreads();

    if (tid < NE) {
        float cs = 0.0f;
#pragma unroll 8
        for (int t = 0; t < TM; t++) cs += ls[t * LSP + tid];
        atomicAdd(&g_eload[tid], cs);
    }
    __threadfence();
    __syncthreads();

    if (tid == 0) {
        int d = atomicAdd(&g_done, 1);
        if (d == gridDim.x - 1) {
            const float invN = 1.0f / (float)N;
            float lb = 0.0f;
            for (int e = 0; e < NE; e++) {
                float dd = g_eload[e] * invN - (1.0f / 64.0f);
                lb += dd * dd;
            }
            out[(size_t)4 * N] = 0.01f * lb + 1e-4f * (g_zsum * invN);
        }
    }
}

// ---------------- block-per-token fixup: parallel scans + MLP-16 dots ----------------
__device__ __forceinline__ void twosum(float& s, float& c, float p) {
    float t  = s + p;
    float bv = t - s;
    c += (s - (t - bv)) + (p - bv);
    s = t;
}

__global__ __launch_bounds__(128) void fixup_kernel(
    const float* __restrict__ x, const float* __restrict__ W,
    float* __restrict__ out, int N)
{
    __shared__ float4 xs4[HDIM / 4];
    __shared__ float  lgs[NE];
    __shared__ int    cand[MAXCAND];
    __shared__ int    ncand_sh;
    __shared__ float  cval[MAXCAND];
    __shared__ int    top_i1, top_i2;
    __shared__ float  red[4];
    const int tid  = threadIdx.x;
    const int wid  = tid >> 5;
    const int lane = tid & 31;
    const int nf   = min(g_nflag, FLAG_CAP);

    for (int fi = blockIdx.x; fi < nf; fi += gridDim.x) {
        const int tg = g_flags[fi];

        const float4* xr4 = reinterpret_cast<const float4*>(&x[(size_t)tg * HDIM]);
#pragma unroll
        for (int i = 0; i < 4; i++)
            xs4[tid + i * 128] = xr4[tid + i * 128];
        if (tid < NE) lgs[tid] = g_flag_lg[fi][tid];
        __syncthreads();

        // warp 0: parallel top-2 values + ballot candidate list (ascending index)
        if (wid == 0) {
            float a = lgs[lane], bb = lgs[lane + 32];
            float v1 = fmaxf(a, bb), v2 = fminf(a, bb);
#pragma unroll
            for (int o = 16; o > 0; o >>= 1) {
                float w1 = __shfl_xor_sync(0xFFFFFFFFu, v1, o);
                float w2 = __shfl_xor_sync(0xFFFFFFFFu, v2, o);
                if (w1 > v1) { v2 = fmaxf(v1, w2); v1 = w1; }
                else         { v2 = fmaxf(v2, w1); }
            }
            float cut = v2 - 2.0f * GAP_TH;
            uint32_t mA = __ballot_sync(0xFFFFFFFFu, a > cut);
            uint32_t mB = __ballot_sync(0xFFFFFFFFu, bb > cut);
            if (lane == 0) {
                int nc = 0;
                while (mA && nc < MAXCAND) { int e = __ffs(mA) - 1; mA &= mA - 1; cand[nc++] = e; }
                while (mB && nc < MAXCAND) { int e = __ffs(mB) - 1; mB &= mB - 1; cand[nc++] = e + 32; }
                ncand_sh = nc;
            }
        }
        __syncthreads();
        const int nc = ncand_sh;

        // 4 warps x concurrent candidates; fully-unrolled MLP-16 dot
        for (int ci = wid; ci < nc; ci += 4) {
            const float4* wr4 = reinterpret_cast<const float4*>(&W[(size_t)cand[ci] * HDIM]);
            float s0 = 0, c0 = 0, s1 = 0, c1 = 0, s2 = 0, c2 = 0, s3 = 0, c3 = 0;
#pragma unroll
            for (int j = 0; j < 16; j++) {
                float4 a = xs4[lane + j * 32];
                float4 bb = wr4[lane + j * 32];
                float p0 = a.x * bb.x; float e0 = fmaf(a.x, bb.x, -p0); twosum(s0, c0, p0); c0 += e0;
                float p1 = a.y * bb.y; float e1 = fmaf(a.y, bb.y, -p1); twosum(s1, c1, p1); c1 += e1;
                float p2 = a.z * bb.z; float e2 = fmaf(a.z, bb.z, -p2); twosum(s2, c2, p2); c2 += e2;
                float p3 = a.w * bb.w; float e3 = fmaf(a.w, bb.w, -p3); twosum(s3, c3, p3); c3 += e3;
            }
            twosum(s0, c0, s1); c0 += c1;
            twosum(s2, c2, s3); c2 += c3;
            twosum(s0, c0, s2); c0 += c2;
#pragma unroll
            for (int o = 16; o > 0; o >>= 1) {
                float ss = __shfl_xor_sync(0xFFFFFFFFu, s0, o);
                float cc = __shfl_xor_sync(0xFFFFFFFFu, c0, o);
                twosum(s0, c0, ss);
                c0 += cc;
            }
            if (lane == 0) cval[ci] = s0 + c0;
        }
        __syncthreads();

        // exact top-2 is among the candidates; ascending-index scan keeps jax tie rule
        if (tid == 0) {
            for (int ci = 0; ci < nc; ci++) lgs[cand[ci]] = cval[ci];
            float v1 = -1e30f, v2 = -1e30f; int i1 = 0, i2 = 0;
            for (int ci = 0; ci < nc; ci++) {
                float le = cval[ci]; int e = cand[ci];
                if (le > v1)      { v2 = v1; i2 = i1; v1 = le; i1 = e; }
                else if (le > v2) { v2 = le; i2 = e; }
            }
            top_i1 = i1; top_i2 = i2;
        }
        __syncthreads();

        // block-parallel softmax sum over corrected logits
        float ev = 0.0f;
        const float m = lgs[top_i1];
        if (tid < NE) ev = expf(lgs[tid] - m);
#pragma unroll
        for (int o = 16; o > 0; o >>= 1)
            ev += __shfl_xor_sync(0xFFFFFFFFu, ev, o);
        if (tid < NE && lane == 0) red[wid] = ev;
        __syncthreads();

        if (tid == 0) {
            float s = red[0] + red[1];
            float inv = 1.0f / s;
            float p1 = inv;
            float p2 = expf(lgs[top_i2] - m) * inv;
            float s1 = 1.0f / (1.0f + expf(p2 - p1));
            out[tg * 2 + 0] = s1;
            out[tg * 2 + 1] = 1.0f - s1;
            out[2 * N + tg * 2 + 0] = (float)top_i1;
            out[2 * N + tg * 2 + 1] = (float)top_i2;
        }
        __syncthreads();
    }
}

extern "C" void kernel_launch(void* const* d_in, const int* in_sizes, int n_in,
                              void* d_out, int out_size) {
    const float* x = (const float*)d_in[0];
    const float* W = (const float*)d_in[1];
    float* out = (float*)d_out;
    const int N = in_sizes[0] / HDIM;   // 16384

    cudaFuncSetAttribute(gateK_kernel, cudaFuncAttributeMaxDynamicSharedMemorySize, SMEM_DYN);
    prep_kernel<<<NE, 128>>>(W);
    gateK_kernel<<<(N / TM) * KSPLIT, THREADS, SMEM_DYN>>>(x, N);
    combine_kernel<<<N / TM, 128>>>(out, N);
    fixup_kernel<<<512, 128>>>(x, W, out, N);
}